// round 4
// baseline (speedup 1.0000x reference)
#include <cuda_runtime.h>

#define NBATCH 1024
#define NV     6890
#define NJ     24
#define NBETA  10
#define NPOSE  207
#define NK     19
#define V3     20670          // NV*3
#define KTOT   218            // 207 pose_feature + 10 shape + 1 (v_template)
#define NVP    6892           // NV padded to /4 for float4 loads

// ---- k2 tiling ----
#define TB   16               // batches per block
#define TC   192              // columns (vertex components) per block
#define TV   64               // vertices per block (TC/3)
#define KT   16               // k-tile
#define K2T  192              // threads in k2

__constant__ int c_parents[NJ] = {0,0,0,0,1,2,3,4,5,6,7,8,9,9,9,12,13,14,16,17,18,19,20,21};

// Scratch (device globals; no allocation allowed)
__device__ float g_coef[NBATCH * KTOT];      // per-batch blend coefficients
__device__ float g_A[NBATCH * NJ * 12];      // per-batch relative transforms, 3x4 rows
__device__ float g_Mjt[NJ * 11 * 3];         // [k][nb(10) | v_template(1)][xyz]
__device__ float g_jrT[NK * NVP];            // transposed, padded joint_regressor

// ---- packed fp32x2 helpers ----
#define FFMA2(d, a, b) asm("fma.rn.f32x2 %0, %1, %2, %0;" : "+l"(d) : "l"(a), "l"(b))
#define PACK2(d, s)    asm("mov.b64 %0, {%1, %1};" : "=l"(d) : "f"(s))
#define UNPACK2(lo, hi, s) asm("mov.b64 {%0, %1}, %2;" : "=f"(lo), "=f"(hi) : "l"(s))

// ---------------------------------------------------------------------------
// K0: M[k,nb,c] = sum_v reg[v,k]*shapedirs[nb, v*3+c];  Jt[k,c] = sum_v reg[v,k]*v_template[v,c]
// ---------------------------------------------------------------------------
__global__ __launch_bounds__(256) void k0_mjt(
    const float* __restrict__ reg,        // [V, 24]
    const float* __restrict__ shapedirs,  // [10, V3]
    const float* __restrict__ v_template) // [V, 3]
{
    int k = blockIdx.x;      // joint
    int col = blockIdx.y;    // 0..9 shapedirs row, 10 = v_template
    int tid = threadIdx.x;
    const float* X = (col < NBETA) ? (shapedirs + (size_t)col * V3) : v_template;
    float a0 = 0.f, a1 = 0.f, a2 = 0.f;
    for (int v = tid; v < NV; v += 256) {
        float r = reg[v * NJ + k];
        a0 += r * X[v * 3 + 0];
        a1 += r * X[v * 3 + 1];
        a2 += r * X[v * 3 + 2];
    }
    __shared__ float s_part[8][3];
    #pragma unroll
    for (int off = 16; off; off >>= 1) {
        a0 += __shfl_down_sync(0xffffffffu, a0, off);
        a1 += __shfl_down_sync(0xffffffffu, a1, off);
        a2 += __shfl_down_sync(0xffffffffu, a2, off);
    }
    int lane = tid & 31, w = tid >> 5;
    if (lane == 0) { s_part[w][0] = a0; s_part[w][1] = a1; s_part[w][2] = a2; }
    __syncthreads();
    if (tid == 0) {
        float r0 = 0.f, r1 = 0.f, r2 = 0.f;
        #pragma unroll
        for (int i = 0; i < 8; i++) { r0 += s_part[i][0]; r1 += s_part[i][1]; r2 += s_part[i][2]; }
        g_Mjt[(k * 11 + col) * 3 + 0] = r0;
        g_Mjt[(k * 11 + col) * 3 + 1] = r1;
        g_Mjt[(k * 11 + col) * 3 + 2] = r2;
    }
}

// ---------------------------------------------------------------------------
// KT0: transpose joint_regressor into [NK][NVP], zero-padded
// ---------------------------------------------------------------------------
__global__ __launch_bounds__(256) void kt_trans(const float* __restrict__ jr) {
    int idx = blockIdx.x * 256 + threadIdx.x;
    if (idx < NK * NVP) {
        int k = idx / NVP, v = idx - k * NVP;
        g_jrT[idx] = (v < NV) ? jr[v * NK + k] : 0.f;
    }
}

// ---------------------------------------------------------------------------
// K1: per-batch Rodrigues, coef vector, joints (via Mjt), kinematic chain, rel A
// ---------------------------------------------------------------------------
__global__ __launch_bounds__(64) void k1_batch(
    const float* __restrict__ in,     // [B, 82]
    float* __restrict__ out_Rs)       // [B, 24, 3, 3]
{
    int b = blockIdx.x, tid = threadIdx.x;
    __shared__ float s_R[NJ][9];
    __shared__ float s_Js[NJ][3];
    __shared__ float s_G[NJ][12];
    const float* pin = in + (size_t)b * 82;

    if (tid < NJ) {
        float ax = pin[tid * 3 + 0], ay = pin[tid * 3 + 1], az = pin[tid * 3 + 2];
        float ang = sqrtf(ax * ax + ay * ay + az * az + 1e-8f);
        float x = ax / ang, y = ay / ang, z = az / ang;
        float cth = cosf(ang), sth = sinf(ang), C = 1.f - cth;
        float R[9];
        R[0] = cth + C * x * x;  R[1] = C * x * y - sth * z; R[2] = C * x * z + sth * y;
        R[3] = C * x * y + sth * z; R[4] = cth + C * y * y;  R[5] = C * y * z - sth * x;
        R[6] = C * x * z - sth * y; R[7] = C * y * z + sth * x; R[8] = cth + C * z * z;
        #pragma unroll
        for (int i = 0; i < 9; i++) {
            s_R[tid][i] = R[i];
            out_Rs[(size_t)b * 216 + tid * 9 + i] = R[i];
        }
        if (tid >= 1) {
            #pragma unroll
            for (int i = 0; i < 9; i++)
                g_coef[(size_t)b * KTOT + (tid - 1) * 9 + i] =
                    R[i] - ((i == 0 || i == 4 || i == 8) ? 1.f : 0.f);
        }
        #pragma unroll
        for (int c = 0; c < 3; c++) {
            float val = g_Mjt[(tid * 11 + 10) * 3 + c];
            #pragma unroll
            for (int nb = 0; nb < NBETA; nb++)
                val += pin[72 + nb] * g_Mjt[(tid * 11 + nb) * 3 + c];
            s_Js[tid][c] = val;
        }
    } else if (tid < NJ + NBETA) {
        g_coef[(size_t)b * KTOT + NPOSE + (tid - NJ)] = pin[72 + (tid - NJ)];
    } else if (tid == NJ + NBETA) {
        g_coef[(size_t)b * KTOT + 217] = 1.f;
    }
    __syncthreads();

    if (tid == 0) {
        #pragma unroll
        for (int r = 0; r < 3; r++) {
            s_G[0][r * 4 + 0] = s_R[0][r * 3 + 0];
            s_G[0][r * 4 + 1] = s_R[0][r * 3 + 1];
            s_G[0][r * 4 + 2] = s_R[0][r * 3 + 2];
            s_G[0][r * 4 + 3] = s_Js[0][r];
        }
        for (int j = 1; j < NJ; j++) {
            int p = c_parents[j];
            float tx = s_Js[j][0] - s_Js[p][0];
            float ty = s_Js[j][1] - s_Js[p][1];
            float tz = s_Js[j][2] - s_Js[p][2];
            #pragma unroll
            for (int r = 0; r < 3; r++) {
                float g0 = s_G[p][r * 4 + 0], g1 = s_G[p][r * 4 + 1];
                float g2 = s_G[p][r * 4 + 2], gt = s_G[p][r * 4 + 3];
                s_G[j][r * 4 + 0] = g0 * s_R[j][0] + g1 * s_R[j][3] + g2 * s_R[j][6];
                s_G[j][r * 4 + 1] = g0 * s_R[j][1] + g1 * s_R[j][4] + g2 * s_R[j][7];
                s_G[j][r * 4 + 2] = g0 * s_R[j][2] + g1 * s_R[j][5] + g2 * s_R[j][8];
                s_G[j][r * 4 + 3] = g0 * tx + g1 * ty + g2 * tz + gt;
            }
        }
    }
    __syncthreads();

    if (tid < NJ) {
        int j = tid;
        #pragma unroll
        for (int r = 0; r < 3; r++) {
            float g0 = s_G[j][r * 4 + 0], g1 = s_G[j][r * 4 + 1], g2 = s_G[j][r * 4 + 2];
            float t = s_G[j][r * 4 + 3] - (g0 * s_Js[j][0] + g1 * s_Js[j][1] + g2 * s_Js[j][2]);
            size_t o = (size_t)b * 288 + j * 12 + r * 4;
            g_A[o + 0] = g0; g_A[o + 1] = g1; g_A[o + 2] = g2; g_A[o + 3] = t;
        }
    }
}

// ---------------------------------------------------------------------------
// K2: fused blendshape GEMM + LBS, fp32x2 packed, small-smem / high-occupancy.
//   Block = 16 batches x 64 vertices (192 columns), 192 threads.
//   GEMM micro-tile: 4 batches x 4 cols = 8 fp32x2 accumulators.
//   Coefs stored pre-duplicated (fp32x2) -> no PACK in the hot loop.
// Dynamic smem (40192 B), phase-overlaid:
//   GEMM:  s_coef2 ull[218][16] @0      (27904 B)
//          s_dirs  f32[16][192] @27904  (12288 B)
//   LBS:   s_V     f32[16][194] @0      (12416 B)
//          s_WT    f32[24][66]  @12416  ( 6336 B)
//          s_A     f32[16][290] @18752  (18560 B)
// ---------------------------------------------------------------------------
#define SMEM_K2 40192

__global__ __launch_bounds__(K2T) void k2_lbs(
    const float* __restrict__ posedirs,   // [207, V3]
    const float* __restrict__ shapedirs,  // [10, V3]
    const float* __restrict__ v_template, // [V3]
    const float* __restrict__ lbsw,       // [V, 24]
    float* __restrict__ out_verts)        // [B, V, 3]
{
    extern __shared__ char smem[];
    unsigned long long* s_coef2 = (unsigned long long*)smem;   // [218][16]
    float* s_dirs = (float*)(smem + 27904);                    // [16][192]
    float* s_V    = (float*)smem;                              // [16][194] overlay
    float* s_WT   = (float*)(smem + 12416);                    // [24][66]  overlay
    float* s_A    = (float*)(smem + 18752);                    // [16][290] overlay

    int tid = threadIdx.x;
    int vbase = blockIdx.x * TV;
    int cbase = vbase * 3;
    int bbase = blockIdx.y * TB;

    // ---- stage coef, pre-duplicated into fp32x2 pairs ----
    for (int i = tid; i < TB * KTOT; i += K2T) {
        int b = i & 15, k = i >> 4;
        float v = g_coef[(size_t)(bbase + b) * KTOT + k];
        unsigned long long dv; PACK2(dv, v);
        s_coef2[k * TB + b] = dv;
    }
    __syncthreads();

    // ---- GEMM phase ----
    int bg = tid / 48, cg = tid - bg * 48;   // 4 batch-groups x 48 col-groups
    int bq = bg * 4;                          // 4 consecutive batches
    int cA = cg * 4;                          // 4 cols (16B LDS.128)

    unsigned long long acc[4][2];
    #pragma unroll
    for (int i = 0; i < 4; i++) { acc[i][0] = 0ull; acc[i][1] = 0ull; }

#define GEMM_STEP(KK)                                                         \
    {                                                                         \
        ulonglong2 c01 = *(const ulonglong2*)&s_coef2[(kt + (KK)) * TB + bq];     \
        ulonglong2 c23 = *(const ulonglong2*)&s_coef2[(kt + (KK)) * TB + bq + 2]; \
        ulonglong2 dd  = *(const ulonglong2*)&s_dirs[(KK) * TC + cA];             \
        FFMA2(acc[0][0], c01.x, dd.x); FFMA2(acc[0][1], c01.x, dd.y);         \
        FFMA2(acc[1][0], c01.y, dd.x); FFMA2(acc[1][1], c01.y, dd.y);         \
        FFMA2(acc[2][0], c23.x, dd.x); FFMA2(acc[2][1], c23.x, dd.y);         \
        FFMA2(acc[3][0], c23.y, dd.x); FFMA2(acc[3][1], c23.y, dd.y);         \
    }

    for (int kt = 0; kt < KTOT; kt += KT) {
        int kmax = min(KT, KTOT - kt);
        for (int i = tid; i < kmax * (TC / 2); i += K2T) {
            int r = i / (TC / 2), c2 = i - r * (TC / 2);
            int col = cbase + c2 * 2;
            int k = kt + r;
            float2 val = make_float2(0.f, 0.f);
            if (col < V3) {
                const float* src;
                if (k < NPOSE)      src = posedirs + (size_t)k * V3;
                else if (k < 217)   src = shapedirs + (size_t)(k - NPOSE) * V3;
                else                src = v_template;
                val = *(const float2*)(src + col);
            }
            *(float2*)&s_dirs[r * TC + c2 * 2] = val;
        }
        __syncthreads();
        if (kmax == KT) {
            #pragma unroll
            for (int kk = 0; kk < KT; kk++) GEMM_STEP(kk)
        } else {
            for (int kk = 0; kk < kmax; kk++) GEMM_STEP(kk)
        }
        __syncthreads();
    }
#undef GEMM_STEP

    // ---- transition: write v_posed tile, stage WT and A (all overlays) ----
    #pragma unroll
    for (int bi = 0; bi < 4; bi++) {
        int b = bq + bi;
        *(unsigned long long*)&s_V[b * 194 + cA]     = acc[bi][0];
        *(unsigned long long*)&s_V[b * 194 + cA + 2] = acc[bi][1];
    }
    for (int i = tid; i < NJ * TV; i += K2T) {
        int j = i >> 6, v = i & 63;
        int gv = vbase + v;
        s_WT[j * 66 + v] = (gv < NV) ? lbsw[(size_t)gv * NJ + j] : 0.f;
    }
    for (int i = tid; i < TB * 144; i += K2T) {
        int b = i / 144, j2 = i - b * 144;
        *(unsigned long long*)&s_A[b * 290 + j2 * 2] =
            *(const unsigned long long*)&g_A[(size_t)(bbase + b) * 288 + j2 * 2];
    }
    __syncthreads();

    // ---- LBS phase: tasks = 8 batch-pairs x 32 vertex-pairs = 256 ----
    for (int t = tid; t < (TB / 2) * 32; t += K2T) {
        int bgp = t >> 5, vg = t & 31;
        int b0 = bgp * 2, b1 = b0 + 1;
        int v0 = vg * 2,  v1 = v0 + 1;

        unsigned long long T00[6], T01[6], T10[6], T11[6];
        #pragma unroll
        for (int r = 0; r < 6; r++) { T00[r] = 0; T01[r] = 0; T10[r] = 0; T11[r] = 0; }

        #pragma unroll 4
        for (int j = 0; j < NJ; j++) {
            float2 w01 = *(const float2*)&s_WT[j * 66 + v0];
            unsigned long long W0, W1;
            PACK2(W0, w01.x); PACK2(W1, w01.y);
            const float* A0 = &s_A[b0 * 290 + j * 12];
            const float* A1 = &s_A[b1 * 290 + j * 12];
            #pragma unroll
            for (int r = 0; r < 6; r++) {
                unsigned long long a0 = *(const unsigned long long*)(A0 + 2 * r);
                unsigned long long a1 = *(const unsigned long long*)(A1 + 2 * r);
                FFMA2(T00[r], W0, a0);
                FFMA2(T01[r], W1, a0);
                FFMA2(T10[r], W0, a1);
                FFMA2(T11[r], W1, a1);
            }
        }

        int gv0 = vbase + v0, gv1 = vbase + v1;
        #pragma unroll
        for (int c = 0; c < 4; c++) {
            const unsigned long long* T = (c == 0) ? T00 : (c == 1) ? T01 : (c == 2) ? T10 : T11;
            int b  = (c < 2) ? b0 : b1;
            int v  = (c & 1) ? v1 : v0;
            int gv = (c & 1) ? gv1 : gv0;
            if (gv >= NV) continue;
            float x = s_V[b * 194 + 3 * v + 0];
            float y = s_V[b * 194 + 3 * v + 1];
            float z = s_V[b * 194 + 3 * v + 2];
            float a0, e0, f0, t0, a1, e1, f1, t1, a2, e2, f2, t2;
            UNPACK2(a0, e0, T[0]); UNPACK2(f0, t0, T[1]);
            UNPACK2(a1, e1, T[2]); UNPACK2(f1, t1, T[3]);
            UNPACK2(a2, e2, T[4]); UNPACK2(f2, t2, T[5]);
            size_t o = ((size_t)(bbase + b) * NV + gv) * 3;
            out_verts[o + 0] = fmaf(a0, x, fmaf(e0, y, fmaf(f0, z, t0)));
            out_verts[o + 1] = fmaf(a1, x, fmaf(e1, y, fmaf(f1, z, t1)));
            out_verts[o + 2] = fmaf(a2, x, fmaf(e2, y, fmaf(f2, z, t2)));
        }
    }
}

// ---------------------------------------------------------------------------
// K3: joints[b,k,c] = sum_v jrT[k][v] * verts[b,v,c]; 2 batches per block to
// halve repeated jrT traffic. float2 vertex loads (rows only 8B-aligned).
// ---------------------------------------------------------------------------
__global__ __launch_bounds__(256) void k3_joints(
    const float* __restrict__ verts,    // [B, V, 3]
    float* __restrict__ out_joints)     // [B, 19, 3]
{
    int b0 = blockIdx.x * 2, tid = threadIdx.x;
    const float* vb0 = verts + (size_t)b0 * V3;
    const float* vb1 = vb0 + V3;
    float acc0[NK * 3], acc1[NK * 3];
    #pragma unroll
    for (int i = 0; i < NK * 3; i++) { acc0[i] = 0.f; acc1[i] = 0.f; }

    const int NQ = (NV + 3) / 4;  // 1723; jrT zero-padded on v=6890,6891
    for (int q = tid; q < NQ; q += 256) {
        int v0 = q * 4;
        const float* p0 = vb0 + v0 * 3;
        const float* p1 = vb1 + v0 * 3;
        float2 a0 = *(const float2*)(p0 + 0), a1 = *(const float2*)(p0 + 2);
        float2 a2 = *(const float2*)(p0 + 4), a3 = *(const float2*)(p0 + 6);
        float2 a4 = *(const float2*)(p0 + 8), a5 = *(const float2*)(p0 + 10);
        float2 c0 = *(const float2*)(p1 + 0), c1 = *(const float2*)(p1 + 2);
        float2 c2 = *(const float2*)(p1 + 4), c3 = *(const float2*)(p1 + 6);
        float2 c4 = *(const float2*)(p1 + 8), c5 = *(const float2*)(p1 + 10);
        #pragma unroll
        for (int k = 0; k < NK; k++) {
            float4 w = *(const float4*)&g_jrT[k * NVP + v0];
            acc0[k * 3 + 0] += w.x * a0.x + w.y * a1.y + w.z * a3.x + w.w * a4.y;
            acc0[k * 3 + 1] += w.x * a0.y + w.y * a2.x + w.z * a3.y + w.w * a5.x;
            acc0[k * 3 + 2] += w.x * a1.x + w.y * a2.y + w.z * a4.x + w.w * a5.y;
            acc1[k * 3 + 0] += w.x * c0.x + w.y * c1.y + w.z * c3.x + w.w * c4.y;
            acc1[k * 3 + 1] += w.x * c0.y + w.y * c2.x + w.z * c3.y + w.w * c5.x;
            acc1[k * 3 + 2] += w.x * c1.x + w.y * c2.y + w.z * c4.x + w.w * c5.y;
        }
    }

    __shared__ float s_part[8][2 * 58];
    int lane = tid & 31, wp = tid >> 5;
    #pragma unroll
    for (int i = 0; i < NK * 3; i++) {
        float v0 = acc0[i], v1 = acc1[i];
        #pragma unroll
        for (int off = 16; off; off >>= 1) {
            v0 += __shfl_down_sync(0xffffffffu, v0, off);
            v1 += __shfl_down_sync(0xffffffffu, v1, off);
        }
        if (lane == 0) { s_part[wp][i] = v0; s_part[wp][58 + i] = v1; }
    }
    __syncthreads();
    if (tid < 2 * NK * 3) {
        int h = tid / (NK * 3), i = tid - h * (NK * 3);
        float s = 0.f;
        #pragma unroll
        for (int w = 0; w < 8; w++) s += s_part[w][h * 58 + i];
        out_joints[(size_t)(b0 + h) * (NK * 3) + i] = s;
    }
}

// ---------------------------------------------------------------------------
extern "C" void kernel_launch(void* const* d_in, const int* in_sizes, int n_in,
                              void* d_out, int out_size) {
    const float* inputs    = (const float*)d_in[0];  // [B, 82]
    const float* v_tmpl    = (const float*)d_in[1];  // [V, 3]
    const float* shapedirs = (const float*)d_in[2];  // [10, V3]
    const float* jreg      = (const float*)d_in[3];  // [V, 24]
    const float* posedirs  = (const float*)d_in[4];  // [207, V3]
    const float* lbsw      = (const float*)d_in[5];  // [V, 24]
    const float* jntreg    = (const float*)d_in[6];  // [V, 19]

    float* out        = (float*)d_out;
    float* out_verts  = out;                                   // B*V*3
    float* out_joints = out + (size_t)NBATCH * NV * 3;         // B*19*3
    float* out_Rs     = out_joints + (size_t)NBATCH * NK * 3;  // B*24*9

    cudaFuncSetAttribute(k2_lbs, cudaFuncAttributeMaxDynamicSharedMemorySize, SMEM_K2);
    cudaFuncSetAttribute(k2_lbs, cudaFuncAttributePreferredSharedMemoryCarveout, 100);

    k0_mjt<<<dim3(NJ, 11), 256>>>(jreg, shapedirs, v_tmpl);
    kt_trans<<<(NK * NVP + 255) / 256, 256>>>(jntreg);
    k1_batch<<<NBATCH, 64>>>(inputs, out_Rs);
    k2_lbs<<<dim3((NV + TV - 1) / TV, NBATCH / TB), K2T, SMEM_K2>>>(
        posedirs, shapedirs, v_tmpl, lbsw, out_verts);
    k3_joints<<<NBATCH / 2, 256>>>(out_verts, out_joints);
}